// round 1
// baseline (speedup 1.0000x reference)
#include <cuda_runtime.h>

#define NMAX 50000
#define EMAX 800000

// ---------------- scratch (device globals; no allocs allowed) ----------------
__device__ __align__(16) int   g_src[EMAX];
__device__ __align__(16) int   g_dst[EMAX];
__device__ int   g_is64;
__device__ __align__(16) float g_deg[NMAX];
__device__ __align__(16) float g_dinv[NMAX];
__device__ __align__(16) float g_dinvc[NMAX];
__device__ __align__(16) float g_el[NMAX];
__device__ __align__(16) float g_er[NMAX];
__device__ __align__(16) float g_m[NMAX];
__device__ __align__(16) float g_z[NMAX];
__device__ __align__(16) float g_nsum[NMAX * 64];
__device__ __align__(16) float g_xw[NMAX * 64];
__device__ __align__(16) float g_h[NMAX * 64];
__device__ __align__(16) float g_accsage[NMAX * 64];
__device__ __align__(16) float g_accgin[NMAX * 64];
__device__ __align__(16) float g_accgcn[NMAX * 64];
__device__ __align__(16) float g_t1[NMAX * 64];
__device__ __align__(16) float g_t2[NMAX * 64];
__device__ __align__(16) float g_accgat[NMAX * 64];

// ---------------- helpers ----------------
__device__ __forceinline__ float eluf(float v) { return v > 0.f ? v : expm1f(v); }
__device__ __forceinline__ float leakyf(float v) { return v > 0.f ? v : 0.2f * v; }

__device__ __forceinline__ void atomicMaxF(float* addr, float v) {
    if (v >= 0.f) atomicMax((int*)addr, __float_as_int(v));
    else          atomicMin((unsigned int*)addr, __float_as_uint(v));
}

// load 64x64 fp32 matrix into smem (all 128 threads)
__device__ __forceinline__ void loadW(float* Wsm, const float* __restrict__ Wg, int t) {
    const float4* s = (const float4*)Wg;
    float4* d = (float4*)Wsm;
#pragma unroll
    for (int i = 0; i < 8; i++) d[t + i * 128] = s[t + i * 128];
}

// acc[16] += sum_k xrow[k] * W[k][jbase + j]
// x row lives in Xs[k4*128 + t] (per-thread column, conflict-free float4 layout)
__device__ __forceinline__ void gemv16(const float* __restrict__ Wsm,
                                       const float4* __restrict__ Xs,
                                       int t, int jbase, float acc[16]) {
#pragma unroll 4
    for (int k4 = 0; k4 < 16; k4++) {
        float4 xq = Xs[k4 * 128 + t];
        const float* wr = Wsm + (k4 * 4) * 64 + jbase;
#pragma unroll
        for (int s = 0; s < 4; s++) {
            float xv = (s == 0) ? xq.x : (s == 1) ? xq.y : (s == 2) ? xq.z : xq.w;
            const float4* wp = (const float4*)(wr + s * 64);
            float4 w0 = wp[0], w1 = wp[1], w2 = wp[2], w3 = wp[3];
            acc[0]  += xv * w0.x; acc[1]  += xv * w0.y; acc[2]  += xv * w0.z; acc[3]  += xv * w0.w;
            acc[4]  += xv * w1.x; acc[5]  += xv * w1.y; acc[6]  += xv * w1.z; acc[7]  += xv * w1.w;
            acc[8]  += xv * w2.x; acc[9]  += xv * w2.y; acc[10] += xv * w2.z; acc[11] += xv * w2.w;
            acc[12] += xv * w3.x; acc[13] += xv * w3.y; acc[14] += xv * w3.z; acc[15] += xv * w3.w;
        }
    }
}

// ---------------- setup kernels ----------------
__global__ void kzero(int N) {
    int total = N * 16;  // float4 elements per big array
    float4 z = make_float4(0.f, 0.f, 0.f, 0.f);
    for (int i = blockIdx.x * blockDim.x + threadIdx.x; i < total;
         i += gridDim.x * blockDim.x) {
        ((float4*)g_nsum)[i] = z;
        ((float4*)g_accgcn)[i] = z;
        ((float4*)g_t1)[i] = z;
        ((float4*)g_t2)[i] = z;
        ((float4*)g_accgat)[i] = z;
        if (i < N) g_deg[i] = 0.f;
    }
}

// edge_index may be int64 (high words all zero) or int32 — detect from layout.
__global__ void kdetect(const int* __restrict__ raw) {
    if (threadIdx.x == 0 && blockIdx.x == 0) {
        int acc = 0;
        for (int k = 0; k < 64; k++) acc |= raw[2 * k + 1];
        g_is64 = (acc == 0) ? 1 : 0;
    }
}

__global__ void kconvert(const void* __restrict__ raw, int E) {
    int is64 = g_is64;
    for (int e = blockIdx.x * blockDim.x + threadIdx.x; e < E;
         e += gridDim.x * blockDim.x) {
        int s, d;
        if (is64) {
            const long long* p = (const long long*)raw;
            s = (int)p[e];
            d = (int)p[(size_t)E + e];
        } else {
            const int* p = (const int*)raw;
            s = p[e];
            d = p[E + e];
        }
        g_src[e] = s;
        g_dst[e] = d;
    }
}

// ---------------- node kernel 1a: all x-based GEMVs ----------------
__global__ __launch_bounds__(128) void k1a(
    const float* __restrict__ x, const float* __restrict__ wts,
    const float* __restrict__ Wmlp, const float* __restrict__ bmlp,
    const float* __restrict__ Wgcn,
    const float* __restrict__ Wgat, const float* __restrict__ asrc,
    const float* __restrict__ adst,
    const float* __restrict__ Wr, const float* __restrict__ bsage,
    const float* __restrict__ Wgin, const float* __restrict__ bgin,
    float* __restrict__ out, int N) {
    __shared__ __align__(16) float Wsm[4096];
    __shared__ float4 Xs[2048];
    int t = threadIdx.x;
    int node = blockIdx.x * 128 + t;
    bool act = node < N;
    if (act) {
        const float4* xr = (const float4*)(x + (size_t)node * 64);
#pragma unroll
        for (int k4 = 0; k4 < 16; k4++) Xs[k4 * 128 + t] = xr[k4];
    }
    // --- W_mlp: out = w0*elu(x@Wmlp + b) ---
    loadW(Wsm, Wmlp, t);
    __syncthreads();
    if (act) {
        float w0 = wts[0];
        float4* o4 = (float4*)(out + (size_t)node * 64);
#pragma unroll
        for (int c = 0; c < 4; c++) {
            float acc[16];
#pragma unroll
            for (int j = 0; j < 16; j++) acc[j] = bmlp[c * 16 + j];
            gemv16(Wsm, Xs, t, c * 16, acc);
#pragma unroll
            for (int j = 0; j < 4; j++)
                o4[c * 4 + j] = make_float4(w0 * eluf(acc[4 * j + 0]),
                                            w0 * eluf(acc[4 * j + 1]),
                                            w0 * eluf(acc[4 * j + 2]),
                                            w0 * eluf(acc[4 * j + 3]));
        }
    }
    __syncthreads();
    // --- W_gcn: xw = x@Wgcn ---
    loadW(Wsm, Wgcn, t);
    __syncthreads();
    if (act) {
        float4* o4 = (float4*)(g_xw + (size_t)node * 64);
#pragma unroll
        for (int c = 0; c < 4; c++) {
            float acc[16] = {};
            gemv16(Wsm, Xs, t, c * 16, acc);
#pragma unroll
            for (int j = 0; j < 4; j++)
                o4[c * 4 + j] = make_float4(acc[4 * j], acc[4 * j + 1],
                                            acc[4 * j + 2], acc[4 * j + 3]);
        }
    }
    __syncthreads();
    // --- W_gat: h = x@Wgat; el = h.a_src; er = h.a_dst ---
    loadW(Wsm, Wgat, t);
    __syncthreads();
    if (act) {
        float el = 0.f, er = 0.f;
        float4* o4 = (float4*)(g_h + (size_t)node * 64);
#pragma unroll
        for (int c = 0; c < 4; c++) {
            float acc[16] = {};
            gemv16(Wsm, Xs, t, c * 16, acc);
#pragma unroll
            for (int j = 0; j < 16; j++) {
                el += acc[j] * asrc[c * 16 + j];
                er += acc[j] * adst[c * 16 + j];
            }
#pragma unroll
            for (int j = 0; j < 4; j++)
                o4[c * 4 + j] = make_float4(acc[4 * j], acc[4 * j + 1],
                                            acc[4 * j + 2], acc[4 * j + 3]);
        }
        g_el[node] = el;
        g_er[node] = er;
    }
    __syncthreads();
    // --- Wr_sage: accsage = x@Wr + b_sage ---
    loadW(Wsm, Wr, t);
    __syncthreads();
    if (act) {
        float4* o4 = (float4*)(g_accsage + (size_t)node * 64);
#pragma unroll
        for (int c = 0; c < 4; c++) {
            float acc[16];
#pragma unroll
            for (int j = 0; j < 16; j++) acc[j] = bsage[c * 16 + j];
            gemv16(Wsm, Xs, t, c * 16, acc);
#pragma unroll
            for (int j = 0; j < 4; j++)
                o4[c * 4 + j] = make_float4(acc[4 * j], acc[4 * j + 1],
                                            acc[4 * j + 2], acc[4 * j + 3]);
        }
    }
    __syncthreads();
    // --- W_gin: accgin = x@Wgin + b_gin ---
    loadW(Wsm, Wgin, t);
    __syncthreads();
    if (act) {
        float4* o4 = (float4*)(g_accgin + (size_t)node * 64);
#pragma unroll
        for (int c = 0; c < 4; c++) {
            float acc[16];
#pragma unroll
            for (int j = 0; j < 16; j++) acc[j] = bgin[c * 16 + j];
            gemv16(Wsm, Xs, t, c * 16, acc);
#pragma unroll
            for (int j = 0; j < 4; j++)
                o4[c * 4 + j] = make_float4(acc[4 * j], acc[4 * j + 1],
                                            acc[4 * j + 2], acc[4 * j + 3]);
        }
    }
}

// ---------------- edge kernel A: deg + nsum ----------------
__global__ __launch_bounds__(256) void ka(const float* __restrict__ x, int E) {
    int tid = blockIdx.x * 256 + threadIdx.x;
    int e = tid >> 2;
    if (e >= E) return;
    int q = tid & 3;
    int s = g_src[e], d = g_dst[e];
    const float4* xs = (const float4*)(x + (size_t)s * 64) + q * 4;
    float* ns = g_nsum + (size_t)d * 64 + q * 16;
#pragma unroll
    for (int j = 0; j < 4; j++) {
        float4 v = __ldg(xs + j);
        atomicAdd(ns + 4 * j + 0, v.x);
        atomicAdd(ns + 4 * j + 1, v.y);
        atomicAdd(ns + 4 * j + 2, v.z);
        atomicAdd(ns + 4 * j + 3, v.w);
    }
    if (q == 0) atomicAdd(&g_deg[d], 1.0f);
}

// ---------------- node kernel 1b: sage + gin finalize, deg-derived scalars ----
__global__ __launch_bounds__(128) void k1b(const float* __restrict__ wts,
                                           const float* __restrict__ Wl,
                                           const float* __restrict__ Wgin,
                                           float* __restrict__ out, int N) {
    __shared__ __align__(16) float Wsm[4096];
    __shared__ float4 Xs[2048];
    int t = threadIdx.x;
    int node = blockIdx.x * 128 + t;
    bool act = node < N;
    float invd = 1.f;
    if (act) {
        const float4* nr = (const float4*)(g_nsum + (size_t)node * 64);
#pragma unroll
        for (int k4 = 0; k4 < 16; k4++) Xs[k4 * 128 + t] = nr[k4];
        float deg = g_deg[node];
        float dmax = fmaxf(deg, 1.f);
        invd = 1.f / dmax;
        g_dinv[node] = rsqrtf(deg + 1.f);
        g_dinvc[node] = rsqrtf(dmax);
        g_m[node] = leakyf(g_el[node] + g_er[node]);  // self-loop init for GAT max
    }
    loadW(Wsm, Wl, t);
    __syncthreads();
    if (act) {
        float w1 = wts[1];
        float4* o4 = (float4*)(out + (size_t)node * 64);
        const float4* as4 = (const float4*)(g_accsage + (size_t)node * 64);
#pragma unroll
        for (int c = 0; c < 4; c++) {
            float acc[16] = {};
            gemv16(Wsm, Xs, t, c * 16, acc);
#pragma unroll
            for (int j = 0; j < 4; j++) {
                float4 ov = o4[c * 4 + j];
                float4 as = as4[c * 4 + j];
                ov.x += w1 * eluf(acc[4 * j + 0] * invd + as.x);
                ov.y += w1 * eluf(acc[4 * j + 1] * invd + as.y);
                ov.z += w1 * eluf(acc[4 * j + 2] * invd + as.z);
                ov.w += w1 * eluf(acc[4 * j + 3] * invd + as.w);
                o4[c * 4 + j] = ov;
            }
        }
    }
    __syncthreads();
    loadW(Wsm, Wgin, t);
    __syncthreads();
    if (act) {
        float w5 = wts[5];
        float4* o4 = (float4*)(out + (size_t)node * 64);
        const float4* gi4 = (const float4*)(g_accgin + (size_t)node * 64);
#pragma unroll
        for (int c = 0; c < 4; c++) {
            float acc[16] = {};
            gemv16(Wsm, Xs, t, c * 16, acc);
#pragma unroll
            for (int j = 0; j < 4; j++) {
                float4 ov = o4[c * 4 + j];
                float4 gi = gi4[c * 4 + j];
                ov.x += w5 * eluf(acc[4 * j + 0] + gi.x);
                ov.y += w5 * eluf(acc[4 * j + 1] + gi.y);
                ov.z += w5 * eluf(acc[4 * j + 2] + gi.z);
                ov.w += w5 * eluf(acc[4 * j + 3] + gi.w);
                o4[c * 4 + j] = ov;
            }
        }
    }
}

// ---------------- edge kernel B: gcn scatter + cheb T1 + gat max ------------
__global__ __launch_bounds__(256) void kb(const float* __restrict__ x, int E) {
    int tid = blockIdx.x * 256 + threadIdx.x;
    int e = tid >> 2;
    if (e >= E) return;
    int q = tid & 3;
    int s = g_src[e], d = g_dst[e];
    float ne = g_dinv[s] * g_dinv[d];
    float nc = g_dinvc[s] * g_dinvc[d];
    const float4* xwv = (const float4*)(g_xw + (size_t)s * 64) + q * 4;
    const float4* xv = (const float4*)(x + (size_t)s * 64) + q * 4;
    float* ag = g_accgcn + (size_t)d * 64 + q * 16;
    float* t1 = g_t1 + (size_t)d * 64 + q * 16;
#pragma unroll
    for (int j = 0; j < 4; j++) {
        float4 a = __ldg(xwv + j);
        atomicAdd(ag + 4 * j + 0, ne * a.x);
        atomicAdd(ag + 4 * j + 1, ne * a.y);
        atomicAdd(ag + 4 * j + 2, ne * a.z);
        atomicAdd(ag + 4 * j + 3, ne * a.w);
        float4 b = __ldg(xv + j);
        atomicAdd(t1 + 4 * j + 0, nc * b.x);
        atomicAdd(t1 + 4 * j + 1, nc * b.y);
        atomicAdd(t1 + 4 * j + 2, nc * b.z);
        atomicAdd(t1 + 4 * j + 3, nc * b.w);
    }
    if (q == 0) {
        float ev = leakyf(g_el[s] + g_er[d]);
        atomicMaxF(&g_m[d], ev);
    }
}

// ---------------- node kernel C: T1 = -acc; z init (self loop) -------------
__global__ void kc(int N) {
    int i = blockIdx.x * blockDim.x + threadIdx.x;
    int total = N * 16;
    if (i < total) {
        float4 v = ((float4*)g_t1)[i];
        ((float4*)g_t1)[i] = make_float4(-v.x, -v.y, -v.z, -v.w);
    }
    if (i < N) {
        float es = leakyf(g_el[i] + g_er[i]);
        g_z[i] = expf(es - g_m[i]);
    }
}

// ---------------- edge kernel D: cheb T2 acc + gat z -----------------------
__global__ __launch_bounds__(256) void kd(int E) {
    int tid = blockIdx.x * 256 + threadIdx.x;
    int e = tid >> 2;
    if (e >= E) return;
    int q = tid & 3;
    int s = g_src[e], d = g_dst[e];
    float nc = g_dinvc[s] * g_dinvc[d];
    const float4* t1v = (const float4*)(g_t1 + (size_t)s * 64) + q * 4;
    float* t2 = g_t2 + (size_t)d * 64 + q * 16;
#pragma unroll
    for (int j = 0; j < 4; j++) {
        float4 v = __ldg(t1v + j);
        atomicAdd(t2 + 4 * j + 0, nc * v.x);
        atomicAdd(t2 + 4 * j + 1, nc * v.y);
        atomicAdd(t2 + 4 * j + 2, nc * v.z);
        atomicAdd(t2 + 4 * j + 3, nc * v.w);
    }
    if (q == 0) {
        float p = expf(leakyf(g_el[s] + g_er[d]) - g_m[d]);
        atomicAdd(&g_z[d], p);
    }
}

// ---------------- edge kernel E: gat weighted sum --------------------------
__global__ __launch_bounds__(256) void ke(int E) {
    int tid = blockIdx.x * 256 + threadIdx.x;
    int e = tid >> 2;
    if (e >= E) return;
    int q = tid & 3;
    int s = g_src[e], d = g_dst[e];
    float co = expf(leakyf(g_el[s] + g_er[d]) - g_m[d]) / (g_z[d] + 1e-16f);
    const float4* hv = (const float4*)(g_h + (size_t)s * 64) + q * 4;
    float* ag = g_accgat + (size_t)d * 64 + q * 16;
#pragma unroll
    for (int j = 0; j < 4; j++) {
        float4 v = __ldg(hv + j);
        atomicAdd(ag + 4 * j + 0, co * v.x);
        atomicAdd(ag + 4 * j + 1, co * v.y);
        atomicAdd(ag + 4 * j + 2, co * v.z);
        atomicAdd(ag + 4 * j + 3, co * v.w);
    }
}

// ---------------- final node kernel: cheb + gcn + gat epilogue --------------
__global__ __launch_bounds__(128) void kf(const float* __restrict__ x,
                                          const float* __restrict__ wts,
                                          const float* __restrict__ Wcheb,
                                          const float* __restrict__ bcheb,
                                          const float* __restrict__ bgcn,
                                          const float* __restrict__ bgat,
                                          float* __restrict__ out, int N) {
    __shared__ __align__(16) float Wsm[4096];
    __shared__ float4 Xs[2048];
    int t = threadIdx.x;
    int node = blockIdx.x * 128 + t;
    bool act = node < N;
    float cacc[64];
    // phase 0: T0 = x through Wcheb[0]
    if (act) {
        const float4* xr = (const float4*)(x + (size_t)node * 64);
#pragma unroll
        for (int k4 = 0; k4 < 16; k4++) Xs[k4 * 128 + t] = xr[k4];
    }
    loadW(Wsm, Wcheb, t);
    __syncthreads();
    if (act) {
#pragma unroll
        for (int c = 0; c < 4; c++) {
            float acc[16];
#pragma unroll
            for (int j = 0; j < 16; j++) acc[j] = bcheb[c * 16 + j];
            gemv16(Wsm, Xs, t, c * 16, acc);
#pragma unroll
            for (int j = 0; j < 16; j++) cacc[c * 16 + j] = acc[j];
        }
    }
    __syncthreads();
    // phase 1: T1 through Wcheb[1]
    if (act) {
        const float4* t1r = (const float4*)(g_t1 + (size_t)node * 64);
#pragma unroll
        for (int k4 = 0; k4 < 16; k4++) Xs[k4 * 128 + t] = t1r[k4];
    }
    loadW(Wsm, Wcheb + 4096, t);
    __syncthreads();
    if (act) {
#pragma unroll
        for (int c = 0; c < 4; c++) {
            float acc[16] = {};
            gemv16(Wsm, Xs, t, c * 16, acc);
#pragma unroll
            for (int j = 0; j < 16; j++) cacc[c * 16 + j] += acc[j];
        }
    }
    __syncthreads();
    // phase 2: T2 = -2*prop(T1) - x through Wcheb[2], plus gcn/gat epilogue
    if (act) {
        const float4* xr = (const float4*)(x + (size_t)node * 64);
        const float4* t2r = (const float4*)(g_t2 + (size_t)node * 64);
#pragma unroll
        for (int k4 = 0; k4 < 16; k4++) {
            float4 a = xr[k4];
            float4 b = t2r[k4];
            Xs[k4 * 128 + t] = make_float4(-2.f * b.x - a.x, -2.f * b.y - a.y,
                                           -2.f * b.z - a.z, -2.f * b.w - a.w);
        }
    }
    loadW(Wsm, Wcheb + 8192, t);
    __syncthreads();
    if (act) {
        float w2 = wts[2], w3 = wts[3], w4 = wts[4];
        float dinv = g_dinv[node];
        float di2 = dinv * dinv;
        float es = leakyf(g_el[node] + g_er[node]);
        float cs = expf(es - g_m[node]) / (g_z[node] + 1e-16f);
        const float4* gc4 = (const float4*)(g_accgcn + (size_t)node * 64);
        const float4* xw4 = (const float4*)(g_xw + (size_t)node * 64);
        const float4* ga4 = (const float4*)(g_accgat + (size_t)node * 64);
        const float4* h4 = (const float4*)(g_h + (size_t)node * 64);
        float4* o4 = (float4*)(out + (size_t)node * 64);
#pragma unroll
        for (int c = 0; c < 4; c++) {
            float acc[16] = {};
            gemv16(Wsm, Xs, t, c * 16, acc);
#pragma unroll
            for (int j = 0; j < 4; j++) {
                float4 gc = gc4[c * 4 + j];
                float4 xwv = xw4[c * 4 + j];
                float4 ga = ga4[c * 4 + j];
                float4 hv = h4[c * 4 + j];
                float4 bg = ((const float4*)bgcn)[c * 4 + j];
                float4 bt = ((const float4*)bgat)[c * 4 + j];
                float4 ov = o4[c * 4 + j];
                ov.x += w2 * eluf(gc.x + xwv.x * di2 + bg.x)
                      + w3 * eluf(ga.x + cs * hv.x + bt.x)
                      + w4 * eluf(cacc[c * 16 + 4 * j + 0] + acc[4 * j + 0]);
                ov.y += w2 * eluf(gc.y + xwv.y * di2 + bg.y)
                      + w3 * eluf(ga.y + cs * hv.y + bt.y)
                      + w4 * eluf(cacc[c * 16 + 4 * j + 1] + acc[4 * j + 1]);
                ov.z += w2 * eluf(gc.z + xwv.z * di2 + bg.z)
                      + w3 * eluf(ga.z + cs * hv.z + bt.z)
                      + w4 * eluf(cacc[c * 16 + 4 * j + 2] + acc[4 * j + 2]);
                ov.w += w2 * eluf(gc.w + xwv.w * di2 + bg.w)
                      + w3 * eluf(ga.w + cs * hv.w + bt.w)
                      + w4 * eluf(cacc[c * 16 + 4 * j + 3] + acc[4 * j + 3]);
                o4[c * 4 + j] = ov;
            }
        }
    }
}

// ---------------- host launcher ----------------
extern "C" void kernel_launch(void* const* d_in, const int* in_sizes, int n_in,
                              void* d_out, int out_size) {
    const float* x     = (const float*)d_in[0];
    const float* wts   = (const float*)d_in[1];
    const float* Wmlp  = (const float*)d_in[2];
    const float* bmlp  = (const float*)d_in[3];
    const float* Wl    = (const float*)d_in[4];
    const float* Wr    = (const float*)d_in[5];
    const float* bsage = (const float*)d_in[6];
    const float* Wgcn  = (const float*)d_in[7];
    const float* bgcn  = (const float*)d_in[8];
    const float* Wgat  = (const float*)d_in[9];
    const float* asrc  = (const float*)d_in[10];
    const float* adst  = (const float*)d_in[11];
    const float* bgat  = (const float*)d_in[12];
    const float* Wcheb = (const float*)d_in[13];
    const float* bcheb = (const float*)d_in[14];
    const float* Wgin  = (const float*)d_in[15];
    const float* bgin  = (const float*)d_in[16];
    const void*  eidx  = d_in[17];
    float* out = (float*)d_out;

    int N = in_sizes[0] / 64;
    if (N > NMAX) N = NMAX;
    int E = in_sizes[17] / 2;
    if (E > EMAX) E = EMAX;

    int nb_node = (N + 127) / 128;
    int nE4 = (E * 4 + 255) / 256;
    int nz = (N * 16 + 255) / 256;

    kzero<<<nz, 256>>>(N);
    kdetect<<<1, 32>>>((const int*)eidx);
    kconvert<<<(E + 255) / 256, 256>>>(eidx, E);
    k1a<<<nb_node, 128>>>(x, wts, Wmlp, bmlp, Wgcn, Wgat, asrc, adst, Wr, bsage,
                          Wgin, bgin, out, N);
    ka<<<nE4, 256>>>(x, E);
    k1b<<<nb_node, 128>>>(wts, Wl, Wgin, out, N);
    kb<<<nE4, 256>>>(x, E);
    kc<<<nz, 256>>>(N);
    kd<<<nE4, 256>>>(E);
    ke<<<nE4, 256>>>(E);
    kf<<<nb_node, 128>>>(x, wts, Wcheb, bcheb, bgcn, bgat, out, N);
}

// round 2
// speedup vs baseline: 2.3068x; 2.3068x over previous
#include <cuda_runtime.h>

#define NMAX 50000
#define EMAX 800000

// ---------------- scratch (device globals; no allocs allowed) ----------------
__device__ __align__(16) int   g_src[EMAX];
__device__ __align__(16) int   g_dst[EMAX];
__device__ __align__(16) int   g_ssrc[EMAX];   // src sorted by dst (CSR adjacency)
__device__ __align__(16) int   g_hist[NMAX];
__device__ __align__(16) int   g_rowptr[NMAX + 1];
__device__ __align__(16) int   g_cnt[NMAX];
__device__ int   g_is64;
__device__ __align__(16) float g_deg[NMAX];
__device__ __align__(16) float g_dinv[NMAX];
__device__ __align__(16) float g_dinvc[NMAX];
__device__ __align__(16) float g_el[NMAX];
__device__ __align__(16) float g_er[NMAX];
__device__ __align__(16) float g_m[NMAX];
__device__ __align__(16) float g_z[NMAX];
__device__ __align__(16) float g_nsum[NMAX * 64];
__device__ __align__(16) float g_xw[NMAX * 64];
__device__ __align__(16) float g_h[NMAX * 64];
__device__ __align__(16) float g_accsage[NMAX * 64];
__device__ __align__(16) float g_accgin[NMAX * 64];
__device__ __align__(16) float g_accgcn[NMAX * 64];
__device__ __align__(16) float g_t1[NMAX * 64];
__device__ __align__(16) float g_t2[NMAX * 64];
__device__ __align__(16) float g_accgat[NMAX * 64];

// ---------------- helpers ----------------
__device__ __forceinline__ float eluf(float v) { return v > 0.f ? v : expm1f(v); }
__device__ __forceinline__ float leakyf(float v) { return v > 0.f ? v : 0.2f * v; }

// load 64x64 fp32 matrix into smem (all 128 threads)
__device__ __forceinline__ void loadW(float* Wsm, const float* __restrict__ Wg, int t) {
    const float4* s = (const float4*)Wg;
    float4* d = (float4*)Wsm;
#pragma unroll
    for (int i = 0; i < 8; i++) d[t + i * 128] = s[t + i * 128];
}

// acc[16] += sum_k xrow[k] * W[k][jbase + j]
__device__ __forceinline__ void gemv16(const float* __restrict__ Wsm,
                                       const float4* __restrict__ Xs,
                                       int t, int jbase, float acc[16]) {
#pragma unroll 4
    for (int k4 = 0; k4 < 16; k4++) {
        float4 xq = Xs[k4 * 128 + t];
        const float* wr = Wsm + (k4 * 4) * 64 + jbase;
#pragma unroll
        for (int s = 0; s < 4; s++) {
            float xv = (s == 0) ? xq.x : (s == 1) ? xq.y : (s == 2) ? xq.z : xq.w;
            const float4* wp = (const float4*)(wr + s * 64);
            float4 w0 = wp[0], w1 = wp[1], w2 = wp[2], w3 = wp[3];
            acc[0]  += xv * w0.x; acc[1]  += xv * w0.y; acc[2]  += xv * w0.z; acc[3]  += xv * w0.w;
            acc[4]  += xv * w1.x; acc[5]  += xv * w1.y; acc[6]  += xv * w1.z; acc[7]  += xv * w1.w;
            acc[8]  += xv * w2.x; acc[9]  += xv * w2.y; acc[10] += xv * w2.z; acc[11] += xv * w2.w;
            acc[12] += xv * w3.x; acc[13] += xv * w3.y; acc[14] += xv * w3.z; acc[15] += xv * w3.w;
        }
    }
}

// ---------------- CSR build ----------------
__global__ void kdetect(const int* __restrict__ raw) {
    if (threadIdx.x == 0 && blockIdx.x == 0) {
        int acc = 0;
        for (int k = 0; k < 64; k++) acc |= raw[2 * k + 1];
        g_is64 = (acc == 0) ? 1 : 0;
    }
}

__global__ void kzeroh(int N) {
    int i = blockIdx.x * blockDim.x + threadIdx.x;
    if (i < N) g_hist[i] = 0;
}

__global__ void kconvert(const void* __restrict__ raw, int E) {
    int is64 = g_is64;
    for (int e = blockIdx.x * blockDim.x + threadIdx.x; e < E;
         e += gridDim.x * blockDim.x) {
        int s, d;
        if (is64) {
            const long long* p = (const long long*)raw;
            s = (int)p[e];
            d = (int)p[(size_t)E + e];
        } else {
            const int* p = (const int*)raw;
            s = p[e];
            d = p[E + e];
        }
        g_src[e] = s;
        g_dst[e] = d;
        atomicAdd(&g_hist[d], 1);
    }
}

// single-block exclusive scan of the histogram; also emits degree scalars
__global__ __launch_bounds__(1024) void kscan(int N, int E) {
    __shared__ int sums[1024];
    int t = threadIdx.x;
    int chunk = (N + 1023) >> 10;
    int beg = t * chunk;
    int end = min(beg + chunk, N);
    int s = 0;
    for (int i = beg; i < end; i++) s += g_hist[i];
    sums[t] = s;
    __syncthreads();
    for (int o = 1; o < 1024; o <<= 1) {
        int v = (t >= o) ? sums[t - o] : 0;
        __syncthreads();
        sums[t] += v;
        __syncthreads();
    }
    int off = (t == 0) ? 0 : sums[t - 1];
    for (int i = beg; i < end; i++) {
        int h = g_hist[i];
        g_rowptr[i] = off;
        g_cnt[i] = off;
        float deg = (float)h;
        g_deg[i] = deg;
        g_dinv[i] = rsqrtf(deg + 1.f);
        g_dinvc[i] = rsqrtf(fmaxf(deg, 1.f));
        off += h;
    }
    if (t == 1023) g_rowptr[N] = E;
}

__global__ void kscatter(int E) {
    int e = blockIdx.x * blockDim.x + threadIdx.x;
    if (e >= E) return;
    int d = g_dst[e];
    int pos = atomicAdd(&g_cnt[d], 1);
    g_ssrc[pos] = g_src[e];
}

// ---------------- node kernel 1a: all x-based GEMVs ----------------
__global__ __launch_bounds__(128) void k1a(
    const float* __restrict__ x, const float* __restrict__ wts,
    const float* __restrict__ Wmlp, const float* __restrict__ bmlp,
    const float* __restrict__ Wgcn,
    const float* __restrict__ Wgat, const float* __restrict__ asrc,
    const float* __restrict__ adst,
    const float* __restrict__ Wr, const float* __restrict__ bsage,
    const float* __restrict__ Wgin, const float* __restrict__ bgin,
    float* __restrict__ out, int N) {
    __shared__ __align__(16) float Wsm[4096];
    __shared__ float4 Xs[2048];
    int t = threadIdx.x;
    int node = blockIdx.x * 128 + t;
    bool act = node < N;
    if (act) {
        const float4* xr = (const float4*)(x + (size_t)node * 64);
#pragma unroll
        for (int k4 = 0; k4 < 16; k4++) Xs[k4 * 128 + t] = xr[k4];
    }
    // --- W_mlp ---
    loadW(Wsm, Wmlp, t);
    __syncthreads();
    if (act) {
        float w0 = wts[0];
        float4* o4 = (float4*)(out + (size_t)node * 64);
#pragma unroll
        for (int c = 0; c < 4; c++) {
            float acc[16];
#pragma unroll
            for (int j = 0; j < 16; j++) acc[j] = bmlp[c * 16 + j];
            gemv16(Wsm, Xs, t, c * 16, acc);
#pragma unroll
            for (int j = 0; j < 4; j++)
                o4[c * 4 + j] = make_float4(w0 * eluf(acc[4 * j + 0]),
                                            w0 * eluf(acc[4 * j + 1]),
                                            w0 * eluf(acc[4 * j + 2]),
                                            w0 * eluf(acc[4 * j + 3]));
        }
    }
    __syncthreads();
    // --- W_gcn ---
    loadW(Wsm, Wgcn, t);
    __syncthreads();
    if (act) {
        float4* o4 = (float4*)(g_xw + (size_t)node * 64);
#pragma unroll
        for (int c = 0; c < 4; c++) {
            float acc[16] = {};
            gemv16(Wsm, Xs, t, c * 16, acc);
#pragma unroll
            for (int j = 0; j < 4; j++)
                o4[c * 4 + j] = make_float4(acc[4 * j], acc[4 * j + 1],
                                            acc[4 * j + 2], acc[4 * j + 3]);
        }
    }
    __syncthreads();
    // --- W_gat ---
    loadW(Wsm, Wgat, t);
    __syncthreads();
    if (act) {
        float el = 0.f, er = 0.f;
        float4* o4 = (float4*)(g_h + (size_t)node * 64);
#pragma unroll
        for (int c = 0; c < 4; c++) {
            float acc[16] = {};
            gemv16(Wsm, Xs, t, c * 16, acc);
#pragma unroll
            for (int j = 0; j < 16; j++) {
                el += acc[j] * asrc[c * 16 + j];
                er += acc[j] * adst[c * 16 + j];
            }
#pragma unroll
            for (int j = 0; j < 4; j++)
                o4[c * 4 + j] = make_float4(acc[4 * j], acc[4 * j + 1],
                                            acc[4 * j + 2], acc[4 * j + 3]);
        }
        g_el[node] = el;
        g_er[node] = er;
    }
    __syncthreads();
    // --- Wr_sage ---
    loadW(Wsm, Wr, t);
    __syncthreads();
    if (act) {
        float4* o4 = (float4*)(g_accsage + (size_t)node * 64);
#pragma unroll
        for (int c = 0; c < 4; c++) {
            float acc[16];
#pragma unroll
            for (int j = 0; j < 16; j++) acc[j] = bsage[c * 16 + j];
            gemv16(Wsm, Xs, t, c * 16, acc);
#pragma unroll
            for (int j = 0; j < 4; j++)
                o4[c * 4 + j] = make_float4(acc[4 * j], acc[4 * j + 1],
                                            acc[4 * j + 2], acc[4 * j + 3]);
        }
    }
    __syncthreads();
    // --- W_gin ---
    loadW(Wsm, Wgin, t);
    __syncthreads();
    if (act) {
        float4* o4 = (float4*)(g_accgin + (size_t)node * 64);
#pragma unroll
        for (int c = 0; c < 4; c++) {
            float acc[16];
#pragma unroll
            for (int j = 0; j < 16; j++) acc[j] = bgin[c * 16 + j];
            gemv16(Wsm, Xs, t, c * 16, acc);
#pragma unroll
            for (int j = 0; j < 4; j++)
                o4[c * 4 + j] = make_float4(acc[4 * j], acc[4 * j + 1],
                                            acc[4 * j + 2], acc[4 * j + 3]);
        }
    }
}

// ---------------- gather pass A: nsum + gcn + T1 + full GAT softmax ---------
// one warp per destination node; lane covers 2 of the 64 features
__global__ __launch_bounds__(256) void kaggA(const float* __restrict__ x, int N) {
    int gw = (blockIdx.x * 256 + threadIdx.x) >> 5;
    if (gw >= N) return;
    int lane = threadIdx.x & 31;
    int d = gw;
    int beg = g_rowptr[d], end = g_rowptr[d + 1];
    float erd = g_er[d];
    float dinvd = g_dinv[d], dinvcd = g_dinvc[d];
    float es = leakyf(g_el[d] + erd);   // self-loop score
    float m = es;
    for (int e = beg + lane; e < end; e += 32)
        m = fmaxf(m, leakyf(g_el[g_ssrc[e]] + erd));
#pragma unroll
    for (int o = 16; o; o >>= 1) m = fmaxf(m, __shfl_xor_sync(0xffffffffu, m, o));

    float ns0 = 0, ns1 = 0, gc0 = 0, gc1 = 0, t10 = 0, t11 = 0, ga0 = 0, ga1 = 0;
    float zacc = 0.f;
    for (int base = beg; base < end; base += 32) {
        int n = min(32, end - base);
        int sj = 0;
        float pj = 0.f, wgj = 0.f, wtj = 0.f;
        if (lane < n) {
            sj = g_ssrc[base + lane];
            pj = expf(leakyf(g_el[sj] + erd) - m);
            wgj = g_dinv[sj] * dinvd;
            wtj = g_dinvc[sj] * dinvcd;
            zacc += pj;
        }
        for (int j = 0; j < n; j++) {
            int s = __shfl_sync(0xffffffffu, sj, j);
            float p = __shfl_sync(0xffffffffu, pj, j);
            float wg = __shfl_sync(0xffffffffu, wgj, j);
            float wt = __shfl_sync(0xffffffffu, wtj, j);
            float2 xv  = ((const float2*)(x + (size_t)s * 64))[lane];
            float2 xwv = ((const float2*)(g_xw + (size_t)s * 64))[lane];
            float2 hv  = ((const float2*)(g_h + (size_t)s * 64))[lane];
            ns0 += xv.x;       ns1 += xv.y;
            t10 -= wt * xv.x;  t11 -= wt * xv.y;   // T1 = -prop(x)
            gc0 += wg * xwv.x; gc1 += wg * xwv.y;
            ga0 += p * hv.x;   ga1 += p * hv.y;
        }
    }
#pragma unroll
    for (int o = 16; o; o >>= 1) zacc += __shfl_xor_sync(0xffffffffu, zacc, o);
    float z = expf(es - m) + zacc;
    float invz = 1.f / (z + 1e-16f);
    ((float2*)(g_nsum   + (size_t)d * 64))[lane] = make_float2(ns0, ns1);
    ((float2*)(g_accgcn + (size_t)d * 64))[lane] = make_float2(gc0, gc1);
    ((float2*)(g_t1     + (size_t)d * 64))[lane] = make_float2(t10, t11);
    ((float2*)(g_accgat + (size_t)d * 64))[lane] = make_float2(ga0 * invz, ga1 * invz);
    if (lane == 0) { g_m[d] = m; g_z[d] = z; }
}

// ---------------- gather pass B: Cheb T2 acc = prop(T1) ----------------
__global__ __launch_bounds__(256) void kaggB(int N) {
    int gw = (blockIdx.x * 256 + threadIdx.x) >> 5;
    if (gw >= N) return;
    int lane = threadIdx.x & 31;
    int d = gw;
    int beg = g_rowptr[d], end = g_rowptr[d + 1];
    float dinvcd = g_dinvc[d];
    float t20 = 0.f, t21 = 0.f;
    for (int base = beg; base < end; base += 32) {
        int n = min(32, end - base);
        int sj = 0;
        float wtj = 0.f;
        if (lane < n) {
            sj = g_ssrc[base + lane];
            wtj = g_dinvc[sj] * dinvcd;
        }
        for (int j = 0; j < n; j++) {
            int s = __shfl_sync(0xffffffffu, sj, j);
            float wt = __shfl_sync(0xffffffffu, wtj, j);
            float2 v = ((const float2*)(g_t1 + (size_t)s * 64))[lane];
            t20 += wt * v.x;
            t21 += wt * v.y;
        }
    }
    ((float2*)(g_t2 + (size_t)d * 64))[lane] = make_float2(t20, t21);
}

// ---------------- node kernel 1b: sage + gin finalize ----------------
__global__ __launch_bounds__(128) void k1b(const float* __restrict__ wts,
                                           const float* __restrict__ Wl,
                                           const float* __restrict__ Wgin,
                                           float* __restrict__ out, int N) {
    __shared__ __align__(16) float Wsm[4096];
    __shared__ float4 Xs[2048];
    int t = threadIdx.x;
    int node = blockIdx.x * 128 + t;
    bool act = node < N;
    float invd = 1.f;
    if (act) {
        const float4* nr = (const float4*)(g_nsum + (size_t)node * 64);
#pragma unroll
        for (int k4 = 0; k4 < 16; k4++) Xs[k4 * 128 + t] = nr[k4];
        invd = 1.f / fmaxf(g_deg[node], 1.f);
    }
    loadW(Wsm, Wl, t);
    __syncthreads();
    if (act) {
        float w1 = wts[1];
        float4* o4 = (float4*)(out + (size_t)node * 64);
        const float4* as4 = (const float4*)(g_accsage + (size_t)node * 64);
#pragma unroll
        for (int c = 0; c < 4; c++) {
            float acc[16] = {};
            gemv16(Wsm, Xs, t, c * 16, acc);
#pragma unroll
            for (int j = 0; j < 4; j++) {
                float4 ov = o4[c * 4 + j];
                float4 as = as4[c * 4 + j];
                ov.x += w1 * eluf(acc[4 * j + 0] * invd + as.x);
                ov.y += w1 * eluf(acc[4 * j + 1] * invd + as.y);
                ov.z += w1 * eluf(acc[4 * j + 2] * invd + as.z);
                ov.w += w1 * eluf(acc[4 * j + 3] * invd + as.w);
                o4[c * 4 + j] = ov;
            }
        }
    }
    __syncthreads();
    loadW(Wsm, Wgin, t);
    __syncthreads();
    if (act) {
        float w5 = wts[5];
        float4* o4 = (float4*)(out + (size_t)node * 64);
        const float4* gi4 = (const float4*)(g_accgin + (size_t)node * 64);
#pragma unroll
        for (int c = 0; c < 4; c++) {
            float acc[16] = {};
            gemv16(Wsm, Xs, t, c * 16, acc);
#pragma unroll
            for (int j = 0; j < 4; j++) {
                float4 ov = o4[c * 4 + j];
                float4 gi = gi4[c * 4 + j];
                ov.x += w5 * eluf(acc[4 * j + 0] + gi.x);
                ov.y += w5 * eluf(acc[4 * j + 1] + gi.y);
                ov.z += w5 * eluf(acc[4 * j + 2] + gi.z);
                ov.w += w5 * eluf(acc[4 * j + 3] + gi.w);
                o4[c * 4 + j] = ov;
            }
        }
    }
}

// ---------------- final node kernel: cheb + gcn + gat epilogue --------------
__global__ __launch_bounds__(128) void kf(const float* __restrict__ x,
                                          const float* __restrict__ wts,
                                          const float* __restrict__ Wcheb,
                                          const float* __restrict__ bcheb,
                                          const float* __restrict__ bgcn,
                                          const float* __restrict__ bgat,
                                          float* __restrict__ out, int N) {
    __shared__ __align__(16) float Wsm[4096];
    __shared__ float4 Xs[2048];
    int t = threadIdx.x;
    int node = blockIdx.x * 128 + t;
    bool act = node < N;
    float cacc[64];
    if (act) {
        const float4* xr = (const float4*)(x + (size_t)node * 64);
#pragma unroll
        for (int k4 = 0; k4 < 16; k4++) Xs[k4 * 128 + t] = xr[k4];
    }
    loadW(Wsm, Wcheb, t);
    __syncthreads();
    if (act) {
#pragma unroll
        for (int c = 0; c < 4; c++) {
            float acc[16];
#pragma unroll
            for (int j = 0; j < 16; j++) acc[j] = bcheb[c * 16 + j];
            gemv16(Wsm, Xs, t, c * 16, acc);
#pragma unroll
            for (int j = 0; j < 16; j++) cacc[c * 16 + j] = acc[j];
        }
    }
    __syncthreads();
    if (act) {
        const float4* t1r = (const float4*)(g_t1 + (size_t)node * 64);
#pragma unroll
        for (int k4 = 0; k4 < 16; k4++) Xs[k4 * 128 + t] = t1r[k4];
    }
    loadW(Wsm, Wcheb + 4096, t);
    __syncthreads();
    if (act) {
#pragma unroll
        for (int c = 0; c < 4; c++) {
            float acc[16] = {};
            gemv16(Wsm, Xs, t, c * 16, acc);
#pragma unroll
            for (int j = 0; j < 16; j++) cacc[c * 16 + j] += acc[j];
        }
    }
    __syncthreads();
    if (act) {
        const float4* xr = (const float4*)(x + (size_t)node * 64);
        const float4* t2r = (const float4*)(g_t2 + (size_t)node * 64);
#pragma unroll
        for (int k4 = 0; k4 < 16; k4++) {
            float4 a = xr[k4];
            float4 b = t2r[k4];
            Xs[k4 * 128 + t] = make_float4(-2.f * b.x - a.x, -2.f * b.y - a.y,
                                           -2.f * b.z - a.z, -2.f * b.w - a.w);
        }
    }
    loadW(Wsm, Wcheb + 8192, t);
    __syncthreads();
    if (act) {
        float w2 = wts[2], w3 = wts[3], w4 = wts[4];
        float dinv = g_dinv[node];
        float di2 = dinv * dinv;
        float es = leakyf(g_el[node] + g_er[node]);
        float cs = expf(es - g_m[node]) / (g_z[node] + 1e-16f);
        const float4* gc4 = (const float4*)(g_accgcn + (size_t)node * 64);
        const float4* xw4 = (const float4*)(g_xw + (size_t)node * 64);
        const float4* ga4 = (const float4*)(g_accgat + (size_t)node * 64);
        const float4* h4 = (const float4*)(g_h + (size_t)node * 64);
        float4* o4 = (float4*)(out + (size_t)node * 64);
#pragma unroll
        for (int c = 0; c < 4; c++) {
            float acc[16] = {};
            gemv16(Wsm, Xs, t, c * 16, acc);
#pragma unroll
            for (int j = 0; j < 4; j++) {
                float4 gc = gc4[c * 4 + j];
                float4 xwv = xw4[c * 4 + j];
                float4 ga = ga4[c * 4 + j];
                float4 hv = h4[c * 4 + j];
                float4 bg = ((const float4*)bgcn)[c * 4 + j];
                float4 bt = ((const float4*)bgat)[c * 4 + j];
                float4 ov = o4[c * 4 + j];
                ov.x += w2 * eluf(gc.x + xwv.x * di2 + bg.x)
                      + w3 * eluf(ga.x + cs * hv.x + bt.x)
                      + w4 * eluf(cacc[c * 16 + 4 * j + 0] + acc[4 * j + 0]);
                ov.y += w2 * eluf(gc.y + xwv.y * di2 + bg.y)
                      + w3 * eluf(ga.y + cs * hv.y + bt.y)
                      + w4 * eluf(cacc[c * 16 + 4 * j + 1] + acc[4 * j + 1]);
                ov.z += w2 * eluf(gc.z + xwv.z * di2 + bg.z)
                      + w3 * eluf(ga.z + cs * hv.z + bt.z)
                      + w4 * eluf(cacc[c * 16 + 4 * j + 2] + acc[4 * j + 2]);
                ov.w += w2 * eluf(gc.w + xwv.w * di2 + bg.w)
                      + w3 * eluf(ga.w + cs * hv.w + bt.w)
                      + w4 * eluf(cacc[c * 16 + 4 * j + 3] + acc[4 * j + 3]);
                o4[c * 4 + j] = ov;
            }
        }
    }
}

// ---------------- host launcher ----------------
extern "C" void kernel_launch(void* const* d_in, const int* in_sizes, int n_in,
                              void* d_out, int out_size) {
    const float* x     = (const float*)d_in[0];
    const float* wts   = (const float*)d_in[1];
    const float* Wmlp  = (const float*)d_in[2];
    const float* bmlp  = (const float*)d_in[3];
    const float* Wl    = (const float*)d_in[4];
    const float* Wr    = (const float*)d_in[5];
    const float* bsage = (const float*)d_in[6];
    const float* Wgcn  = (const float*)d_in[7];
    const float* bgcn  = (const float*)d_in[8];
    const float* Wgat  = (const float*)d_in[9];
    const float* asrc  = (const float*)d_in[10];
    const float* adst  = (const float*)d_in[11];
    const float* bgat  = (const float*)d_in[12];
    const float* Wcheb = (const float*)d_in[13];
    const float* bcheb = (const float*)d_in[14];
    const float* Wgin  = (const float*)d_in[15];
    const float* bgin  = (const float*)d_in[16];
    const void*  eidx  = d_in[17];
    float* out = (float*)d_out;

    int N = in_sizes[0] / 64;
    if (N > NMAX) N = NMAX;
    int E = in_sizes[17] / 2;
    if (E > EMAX) E = EMAX;

    int nb_node = (N + 127) / 128;
    int nb_warp = (N * 32 + 255) / 256;

    kdetect<<<1, 32>>>((const int*)eidx);
    kzeroh<<<(N + 255) / 256, 256>>>(N);
    kconvert<<<(E + 255) / 256, 256>>>(eidx, E);
    kscan<<<1, 1024>>>(N, E);
    kscatter<<<(E + 255) / 256, 256>>>(E);
    k1a<<<nb_node, 128>>>(x, wts, Wmlp, bmlp, Wgcn, Wgat, asrc, adst, Wr, bsage,
                          Wgin, bgin, out, N);
    kaggA<<<nb_warp, 256>>>(x, N);
    k1b<<<nb_node, 128>>>(wts, Wl, Wgin, out, N);
    kaggB<<<nb_warp, 256>>>(N);
    kf<<<nb_node, 128>>>(x, wts, Wcheb, bcheb, bgcn, bgat, out, N);
}

// round 3
// speedup vs baseline: 3.7706x; 1.6345x over previous
#include <cuda_runtime.h>

#define NMAX 50000
#define EMAX 800000

// ---------------- scratch ----------------
__device__ __align__(16) int   g_src[EMAX];
__device__ __align__(16) int   g_dst[EMAX];
__device__ __align__(16) int   g_ssrc[EMAX];
__device__ __align__(16) int   g_hist[NMAX];
__device__ __align__(16) int   g_rowptr[NMAX + 1];
__device__ __align__(16) int   g_cnt[NMAX];
__device__ __align__(16) int   g_bsum[256];
__device__ __align__(16) int   g_boff[256];
__device__ int   g_is64;
__device__ __align__(16) float g_deg[NMAX];
__device__ __align__(16) float g_dinv[NMAX];
__device__ __align__(16) float g_dinvc[NMAX];
__device__ __align__(16) float g_el[NMAX];
__device__ __align__(16) float g_er[NMAX];
__device__ __align__(16) float g_m[NMAX];
__device__ __align__(16) float g_z[NMAX];
__device__ __align__(16) float g_nsum[NMAX * 64];
__device__ __align__(16) float g_xw[NMAX * 64];
__device__ __align__(16) float g_h[NMAX * 64];
__device__ __align__(16) float g_accsage[NMAX * 64];
__device__ __align__(16) float g_accgin[NMAX * 64];
__device__ __align__(16) float g_accgcn[NMAX * 64];
__device__ __align__(16) float g_t1[NMAX * 64];
__device__ __align__(16) float g_t2[NMAX * 64];
__device__ __align__(16) float g_accgat[NMAX * 64];

// ---------------- helpers ----------------
__device__ __forceinline__ float eluf(float v) { return v > 0.f ? v : expm1f(v); }
__device__ __forceinline__ float leakyf(float v) { return v > 0.f ? v : 0.2f * v; }

// load 64x64 fp32 matrix into smem (256 threads)
__device__ __forceinline__ void loadW(float* Wsm, const float* __restrict__ Wg, int t) {
    const float4* s = (const float4*)Wg;
    float4* d = (float4*)Wsm;
#pragma unroll
    for (int i = 0; i < 4; i++) d[t + i * 256] = s[t + i * 256];
}

// acc[16] += sum_k xrow[k] * W[k][jbase + j]
__device__ __forceinline__ void gemv16(const float* __restrict__ Wsm,
                                       const float4* __restrict__ Xs,
                                       int tt, int jbase, float acc[16]) {
#pragma unroll 4
    for (int k4 = 0; k4 < 16; k4++) {
        float4 xq = Xs[k4 * 128 + tt];
        const float* wr = Wsm + (k4 * 4) * 64 + jbase;
#pragma unroll
        for (int s = 0; s < 4; s++) {
            float xv = (s == 0) ? xq.x : (s == 1) ? xq.y : (s == 2) ? xq.z : xq.w;
            const float4* wp = (const float4*)(wr + s * 64);
            float4 w0 = wp[0], w1 = wp[1], w2 = wp[2], w3 = wp[3];
            acc[0]  += xv * w0.x; acc[1]  += xv * w0.y; acc[2]  += xv * w0.z; acc[3]  += xv * w0.w;
            acc[4]  += xv * w1.x; acc[5]  += xv * w1.y; acc[6]  += xv * w1.z; acc[7]  += xv * w1.w;
            acc[8]  += xv * w2.x; acc[9]  += xv * w2.y; acc[10] += xv * w2.z; acc[11] += xv * w2.w;
            acc[12] += xv * w3.x; acc[13] += xv * w3.y; acc[14] += xv * w3.z; acc[15] += xv * w3.w;
        }
    }
}

// half-split Xs loader: half 0 loads k4 0..7, half 1 loads 8..15
__device__ __forceinline__ void loadXs(float4* Xs, const float4* __restrict__ row,
                                       int tt, int half) {
#pragma unroll
    for (int i = 0; i < 8; i++) {
        int k4 = half * 8 + i;
        Xs[k4 * 128 + tt] = row[k4];
    }
}

// ---------------- CSR build ----------------
__global__ void kdetect(const int* __restrict__ raw) {
    if (threadIdx.x == 0 && blockIdx.x == 0) {
        int acc = 0;
        for (int k = 0; k < 64; k++) acc |= raw[2 * k + 1];
        g_is64 = (acc == 0) ? 1 : 0;
    }
}

__global__ void kzeroh(int N) {
    int i = blockIdx.x * blockDim.x + threadIdx.x;
    if (i < N) g_hist[i] = 0;
}

__global__ void kconvert(const void* __restrict__ raw, int E) {
    int is64 = g_is64;
    for (int e = blockIdx.x * blockDim.x + threadIdx.x; e < E;
         e += gridDim.x * blockDim.x) {
        int s, d;
        if (is64) {
            const long long* p = (const long long*)raw;
            s = (int)p[e];
            d = (int)p[(size_t)E + e];
        } else {
            const int* p = (const int*)raw;
            s = p[e];
            d = p[E + e];
        }
        g_src[e] = s;
        g_dst[e] = d;
        atomicAdd(&g_hist[d], 1);
    }
}

// scan stage 1: per-block sums of hist (256 elems per block)
__global__ __launch_bounds__(256) void kbsum(int N) {
    __shared__ int red[256];
    int t = threadIdx.x;
    int i = blockIdx.x * 256 + t;
    red[t] = (i < N) ? g_hist[i] : 0;
    __syncthreads();
    for (int o = 128; o; o >>= 1) {
        if (t < o) red[t] += red[t + o];
        __syncthreads();
    }
    if (t == 0) g_bsum[blockIdx.x] = red[0];
}

// scan stage 2: single-block exclusive scan of G (<=256) block sums
__global__ __launch_bounds__(256) void kbscan(int G) {
    __shared__ int s[256];
    int t = threadIdx.x;
    int v = (t < G) ? g_bsum[t] : 0;
    s[t] = v;
    __syncthreads();
    for (int o = 1; o < 256; o <<= 1) {
        int u = (t >= o) ? s[t - o] : 0;
        __syncthreads();
        s[t] += u;
        __syncthreads();
    }
    if (t < G) g_boff[t] = s[t] - v;
}

// scan stage 3: block-local exclusive scan + block offset; emit rowptr + degree scalars
__global__ __launch_bounds__(256) void kapply(int N, int E) {
    __shared__ int wsum[8];
    int t = threadIdx.x;
    int lane = t & 31, wid = t >> 5;
    int i = blockIdx.x * 256 + t;
    int h = (i < N) ? g_hist[i] : 0;
    int val = h;
#pragma unroll
    for (int o = 1; o < 32; o <<= 1) {
        int u = __shfl_up_sync(0xffffffffu, val, o);
        if (lane >= o) val += u;
    }
    if (lane == 31) wsum[wid] = val;
    __syncthreads();
    if (t < 8) {
        int w = wsum[t];
#pragma unroll
        for (int o = 1; o < 8; o <<= 1) {
            int u = __shfl_up_sync(0xffu, w, o);
            if (t >= o) w += u;
        }
        wsum[t] = w;
    }
    __syncthreads();
    int excl = val - h + (wid ? wsum[wid - 1] : 0) + g_boff[blockIdx.x];
    if (i < N) {
        g_rowptr[i] = excl;
        g_cnt[i] = excl;
        float deg = (float)h;
        g_deg[i] = deg;
        g_dinv[i] = rsqrtf(deg + 1.f);
        g_dinvc[i] = rsqrtf(fmaxf(deg, 1.f));
    }
    if (i == 0) g_rowptr[N] = E;
}

__global__ void kscatter(int E) {
    int e = blockIdx.x * blockDim.x + threadIdx.x;
    if (e >= E) return;
    int d = g_dst[e];
    int pos = atomicAdd(&g_cnt[d], 1);
    g_ssrc[pos] = g_src[e];
}

// ---------------- node kernel 1a: all x-based GEMVs ----------------
// 256 threads / 128 nodes: thread half 0 computes cols 0..31, half 1 cols 32..63
__global__ __launch_bounds__(256) void k1a(
    const float* __restrict__ x, const float* __restrict__ wts,
    const float* __restrict__ Wmlp, const float* __restrict__ bmlp,
    const float* __restrict__ Wgcn,
    const float* __restrict__ Wgat, const float* __restrict__ asrc,
    const float* __restrict__ adst,
    const float* __restrict__ Wr, const float* __restrict__ bsage,
    const float* __restrict__ Wgin, const float* __restrict__ bgin,
    float* __restrict__ out, int N) {
    __shared__ __align__(16) float Wsm[4096];
    __shared__ float4 Xs[2048];
    __shared__ float els[128], ers[128];
    int t = threadIdx.x;
    int tt = t & 127, half = t >> 7;
    int node = blockIdx.x * 128 + tt;
    bool act = node < N;
    if (act) loadXs(Xs, (const float4*)(x + (size_t)node * 64), tt, half);
    // --- W_mlp ---
    loadW(Wsm, Wmlp, t);
    __syncthreads();
    if (act) {
        float w0 = wts[0];
        float4* o4 = (float4*)(out + (size_t)node * 64);
#pragma unroll
        for (int c = 0; c < 2; c++) {
            int cc = half * 2 + c;
            float acc[16];
#pragma unroll
            for (int j = 0; j < 16; j++) acc[j] = bmlp[cc * 16 + j];
            gemv16(Wsm, Xs, tt, cc * 16, acc);
#pragma unroll
            for (int j = 0; j < 4; j++)
                o4[cc * 4 + j] = make_float4(w0 * eluf(acc[4 * j + 0]),
                                             w0 * eluf(acc[4 * j + 1]),
                                             w0 * eluf(acc[4 * j + 2]),
                                             w0 * eluf(acc[4 * j + 3]));
        }
    }
    __syncthreads();
    // --- W_gcn ---
    loadW(Wsm, Wgcn, t);
    __syncthreads();
    if (act) {
        float4* o4 = (float4*)(g_xw + (size_t)node * 64);
#pragma unroll
        for (int c = 0; c < 2; c++) {
            int cc = half * 2 + c;
            float acc[16] = {};
            gemv16(Wsm, Xs, tt, cc * 16, acc);
#pragma unroll
            for (int j = 0; j < 4; j++)
                o4[cc * 4 + j] = make_float4(acc[4 * j], acc[4 * j + 1],
                                             acc[4 * j + 2], acc[4 * j + 3]);
        }
    }
    __syncthreads();
    // --- W_gat ---
    loadW(Wsm, Wgat, t);
    __syncthreads();
    {
        float el = 0.f, er = 0.f;
        if (act) {
            float4* o4 = (float4*)(g_h + (size_t)node * 64);
#pragma unroll
            for (int c = 0; c < 2; c++) {
                int cc = half * 2 + c;
                float acc[16] = {};
                gemv16(Wsm, Xs, tt, cc * 16, acc);
#pragma unroll
                for (int j = 0; j < 16; j++) {
                    el += acc[j] * asrc[cc * 16 + j];
                    er += acc[j] * adst[cc * 16 + j];
                }
#pragma unroll
                for (int j = 0; j < 4; j++)
                    o4[cc * 4 + j] = make_float4(acc[4 * j], acc[4 * j + 1],
                                                 acc[4 * j + 2], acc[4 * j + 3]);
            }
        }
        if (half == 1) { els[tt] = el; ers[tt] = er; }
        __syncthreads();
        if (half == 0 && act) {
            g_el[node] = el + els[tt];
            g_er[node] = er + ers[tt];
        }
    }
    __syncthreads();
    // --- Wr_sage ---
    loadW(Wsm, Wr, t);
    __syncthreads();
    if (act) {
        float4* o4 = (float4*)(g_accsage + (size_t)node * 64);
#pragma unroll
        for (int c = 0; c < 2; c++) {
            int cc = half * 2 + c;
            float acc[16];
#pragma unroll
            for (int j = 0; j < 16; j++) acc[j] = bsage[cc * 16 + j];
            gemv16(Wsm, Xs, tt, cc * 16, acc);
#pragma unroll
            for (int j = 0; j < 4; j++)
                o4[cc * 4 + j] = make_float4(acc[4 * j], acc[4 * j + 1],
                                             acc[4 * j + 2], acc[4 * j + 3]);
        }
    }
    __syncthreads();
    // --- W_gin ---
    loadW(Wsm, Wgin, t);
    __syncthreads();
    if (act) {
        float4* o4 = (float4*)(g_accgin + (size_t)node * 64);
#pragma unroll
        for (int c = 0; c < 2; c++) {
            int cc = half * 2 + c;
            float acc[16];
#pragma unroll
            for (int j = 0; j < 16; j++) acc[j] = bgin[cc * 16 + j];
            gemv16(Wsm, Xs, tt, cc * 16, acc);
#pragma unroll
            for (int j = 0; j < 4; j++)
                o4[cc * 4 + j] = make_float4(acc[4 * j], acc[4 * j + 1],
                                             acc[4 * j + 2], acc[4 * j + 3]);
        }
    }
}

// ---------------- gather pass A: nsum + gcn + T1 + full GAT softmax ---------
__global__ __launch_bounds__(256) void kaggA(const float* __restrict__ x, int N) {
    int gw = (blockIdx.x * 256 + threadIdx.x) >> 5;
    if (gw >= N) return;
    int lane = threadIdx.x & 31;
    int d = gw;
    int beg = g_rowptr[d], end = g_rowptr[d + 1];
    float erd = g_er[d];
    float dinvd = g_dinv[d], dinvcd = g_dinvc[d];
    float es = leakyf(g_el[d] + erd);
    float m = es;
    for (int e = beg + lane; e < end; e += 32)
        m = fmaxf(m, leakyf(g_el[g_ssrc[e]] + erd));
#pragma unroll
    for (int o = 16; o; o >>= 1) m = fmaxf(m, __shfl_xor_sync(0xffffffffu, m, o));

    float ns0 = 0, ns1 = 0, gc0 = 0, gc1 = 0, t10 = 0, t11 = 0, ga0 = 0, ga1 = 0;
    float zacc = 0.f;
    for (int base = beg; base < end; base += 32) {
        int n = min(32, end - base);
        int sj = 0;
        float pj = 0.f, wgj = 0.f, wtj = 0.f;
        if (lane < n) {
            sj = g_ssrc[base + lane];
            pj = expf(leakyf(g_el[sj] + erd) - m);
            wgj = g_dinv[sj] * dinvd;
            wtj = g_dinvc[sj] * dinvcd;
            zacc += pj;
        }
        for (int j = 0; j < n; j++) {
            int s = __shfl_sync(0xffffffffu, sj, j);
            float p = __shfl_sync(0xffffffffu, pj, j);
            float wg = __shfl_sync(0xffffffffu, wgj, j);
            float wt = __shfl_sync(0xffffffffu, wtj, j);
            float2 xv  = ((const float2*)(x + (size_t)s * 64))[lane];
            float2 xwv = ((const float2*)(g_xw + (size_t)s * 64))[lane];
            float2 hv  = ((const float2*)(g_h + (size_t)s * 64))[lane];
            ns0 += xv.x;       ns1 += xv.y;
            t10 -= wt * xv.x;  t11 -= wt * xv.y;
            gc0 += wg * xwv.x; gc1 += wg * xwv.y;
            ga0 += p * hv.x;   ga1 += p * hv.y;
        }
    }
#pragma unroll
    for (int o = 16; o; o >>= 1) zacc += __shfl_xor_sync(0xffffffffu, zacc, o);
    float z = expf(es - m) + zacc;
    float invz = 1.f / (z + 1e-16f);
    ((float2*)(g_nsum   + (size_t)d * 64))[lane] = make_float2(ns0, ns1);
    ((float2*)(g_accgcn + (size_t)d * 64))[lane] = make_float2(gc0, gc1);
    ((float2*)(g_t1     + (size_t)d * 64))[lane] = make_float2(t10, t11);
    ((float2*)(g_accgat + (size_t)d * 64))[lane] = make_float2(ga0 * invz, ga1 * invz);
    if (lane == 0) { g_m[d] = m; g_z[d] = z; }
}

// ---------------- gather pass B: Cheb T2 acc = prop(T1) ----------------
__global__ __launch_bounds__(256) void kaggB(int N) {
    int gw = (blockIdx.x * 256 + threadIdx.x) >> 5;
    if (gw >= N) return;
    int lane = threadIdx.x & 31;
    int d = gw;
    int beg = g_rowptr[d], end = g_rowptr[d + 1];
    float dinvcd = g_dinvc[d];
    float t20 = 0.f, t21 = 0.f;
    for (int base = beg; base < end; base += 32) {
        int n = min(32, end - base);
        int sj = 0;
        float wtj = 0.f;
        if (lane < n) {
            sj = g_ssrc[base + lane];
            wtj = g_dinvc[sj] * dinvcd;
        }
        for (int j = 0; j < n; j++) {
            int s = __shfl_sync(0xffffffffu, sj, j);
            float wt = __shfl_sync(0xffffffffu, wtj, j);
            float2 v = ((const float2*)(g_t1 + (size_t)s * 64))[lane];
            t20 += wt * v.x;
            t21 += wt * v.y;
        }
    }
    ((float2*)(g_t2 + (size_t)d * 64))[lane] = make_float2(t20, t21);
}

// ---------------- node kernel 1b: sage + gin finalize ----------------
__global__ __launch_bounds__(256) void k1b(const float* __restrict__ wts,
                                           const float* __restrict__ Wl,
                                           const float* __restrict__ Wgin,
                                           float* __restrict__ out, int N) {
    __shared__ __align__(16) float Wsm[4096];
    __shared__ float4 Xs[2048];
    int t = threadIdx.x;
    int tt = t & 127, half = t >> 7;
    int node = blockIdx.x * 128 + tt;
    bool act = node < N;
    float invd = 1.f;
    if (act) {
        loadXs(Xs, (const float4*)(g_nsum + (size_t)node * 64), tt, half);
        invd = 1.f / fmaxf(g_deg[node], 1.f);
    }
    loadW(Wsm, Wl, t);
    __syncthreads();
    if (act) {
        float w1 = wts[1];
        float4* o4 = (float4*)(out + (size_t)node * 64);
        const float4* as4 = (const float4*)(g_accsage + (size_t)node * 64);
#pragma unroll
        for (int c = 0; c < 2; c++) {
            int cc = half * 2 + c;
            float acc[16] = {};
            gemv16(Wsm, Xs, tt, cc * 16, acc);
#pragma unroll
            for (int j = 0; j < 4; j++) {
                float4 ov = o4[cc * 4 + j];
                float4 as = as4[cc * 4 + j];
                ov.x += w1 * eluf(acc[4 * j + 0] * invd + as.x);
                ov.y += w1 * eluf(acc[4 * j + 1] * invd + as.y);
                ov.z += w1 * eluf(acc[4 * j + 2] * invd + as.z);
                ov.w += w1 * eluf(acc[4 * j + 3] * invd + as.w);
                o4[cc * 4 + j] = ov;
            }
        }
    }
    __syncthreads();
    loadW(Wsm, Wgin, t);
    __syncthreads();
    if (act) {
        float w5 = wts[5];
        float4* o4 = (float4*)(out + (size_t)node * 64);
        const float4* gi4 = (const float4*)(g_accgin + (size_t)node * 64);
#pragma unroll
        for (int c = 0; c < 2; c++) {
            int cc = half * 2 + c;
            float acc[16] = {};
            gemv16(Wsm, Xs, tt, cc * 16, acc);
#pragma unroll
            for (int j = 0; j < 4; j++) {
                float4 ov = o4[cc * 4 + j];
                float4 gi = gi4[cc * 4 + j];
                ov.x += w5 * eluf(acc[4 * j + 0] + gi.x);
                ov.y += w5 * eluf(acc[4 * j + 1] + gi.y);
                ov.z += w5 * eluf(acc[4 * j + 2] + gi.z);
                ov.w += w5 * eluf(acc[4 * j + 3] + gi.w);
                o4[cc * 4 + j] = ov;
            }
        }
    }
}

// ---------------- final node kernel: cheb + gcn + gat epilogue --------------
__global__ __launch_bounds__(256) void kf(const float* __restrict__ x,
                                          const float* __restrict__ wts,
                                          const float* __restrict__ Wcheb,
                                          const float* __restrict__ bcheb,
                                          const float* __restrict__ bgcn,
                                          const float* __restrict__ bgat,
                                          float* __restrict__ out, int N) {
    __shared__ __align__(16) float Wsm[4096];
    __shared__ float4 Xs[2048];
    int t = threadIdx.x;
    int tt = t & 127, half = t >> 7;
    int node = blockIdx.x * 128 + tt;
    bool act = node < N;
    float cacc[32];
    if (act) loadXs(Xs, (const float4*)(x + (size_t)node * 64), tt, half);
    loadW(Wsm, Wcheb, t);
    __syncthreads();
    if (act) {
#pragma unroll
        for (int c = 0; c < 2; c++) {
            int cc = half * 2 + c;
            float acc[16];
#pragma unroll
            for (int j = 0; j < 16; j++) acc[j] = bcheb[cc * 16 + j];
            gemv16(Wsm, Xs, tt, cc * 16, acc);
#pragma unroll
            for (int j = 0; j < 16; j++) cacc[c * 16 + j] = acc[j];
        }
    }
    __syncthreads();
    if (act) loadXs(Xs, (const float4*)(g_t1 + (size_t)node * 64), tt, half);
    loadW(Wsm, Wcheb + 4096, t);
    __syncthreads();
    if (act) {
#pragma unroll
        for (int c = 0; c < 2; c++) {
            int cc = half * 2 + c;
            float acc[16] = {};
            gemv16(Wsm, Xs, tt, cc * 16, acc);
#pragma unroll
            for (int j = 0; j < 16; j++) cacc[c * 16 + j] += acc[j];
        }
    }
    __syncthreads();
    if (act) {
        const float4* xr = (const float4*)(x + (size_t)node * 64);
        const float4* t2r = (const float4*)(g_t2 + (size_t)node * 64);
#pragma unroll
        for (int i = 0; i < 8; i++) {
            int k4 = half * 8 + i;
            float4 a = xr[k4];
            float4 b = t2r[k4];
            Xs[k4 * 128 + tt] = make_float4(-2.f * b.x - a.x, -2.f * b.y - a.y,
                                            -2.f * b.z - a.z, -2.f * b.w - a.w);
        }
    }
    loadW(Wsm, Wcheb + 8192, t);
    __syncthreads();
    if (act) {
        float w2 = wts[2], w3 = wts[3], w4 = wts[4];
        float dinv = g_dinv[node];
        float di2 = dinv * dinv;
        float es = leakyf(g_el[node] + g_er[node]);
        float cs = expf(es - g_m[node]) / (g_z[node] + 1e-16f);
        const float4* gc4 = (const float4*)(g_accgcn + (size_t)node * 64);
        const float4* xw4 = (const float4*)(g_xw + (size_t)node * 64);
        const float4* ga4 = (const float4*)(g_accgat + (size_t)node * 64);
        const float4* h4 = (const float4*)(g_h + (size_t)node * 64);
        float4* o4 = (float4*)(out + (size_t)node * 64);
#pragma unroll
        for (int c = 0; c < 2; c++) {
            int cc = half * 2 + c;
            float acc[16] = {};
            gemv16(Wsm, Xs, tt, cc * 16, acc);
#pragma unroll
            for (int j = 0; j < 4; j++) {
                float4 gc = gc4[cc * 4 + j];
                float4 xwv = xw4[cc * 4 + j];
                float4 ga = ga4[cc * 4 + j];
                float4 hv = h4[cc * 4 + j];
                float4 bg = ((const float4*)bgcn)[cc * 4 + j];
                float4 bt = ((const float4*)bgat)[cc * 4 + j];
                float4 ov = o4[cc * 4 + j];
                ov.x += w2 * eluf(gc.x + xwv.x * di2 + bg.x)
                      + w3 * eluf(ga.x + cs * hv.x + bt.x)
                      + w4 * eluf(cacc[c * 16 + 4 * j + 0] + acc[4 * j + 0]);
                ov.y += w2 * eluf(gc.y + xwv.y * di2 + bg.y)
                      + w3 * eluf(ga.y + cs * hv.y + bt.y)
                      + w4 * eluf(cacc[c * 16 + 4 * j + 1] + acc[4 * j + 1]);
                ov.z += w2 * eluf(gc.z + xwv.z * di2 + bg.z)
                      + w3 * eluf(ga.z + cs * hv.z + bt.z)
                      + w4 * eluf(cacc[c * 16 + 4 * j + 2] + acc[4 * j + 2]);
                ov.w += w2 * eluf(gc.w + xwv.w * di2 + bg.w)
                      + w3 * eluf(ga.w + cs * hv.w + bt.w)
                      + w4 * eluf(cacc[c * 16 + 4 * j + 3] + acc[4 * j + 3]);
                o4[cc * 4 + j] = ov;
            }
        }
    }
}

// ---------------- host launcher ----------------
extern "C" void kernel_launch(void* const* d_in, const int* in_sizes, int n_in,
                              void* d_out, int out_size) {
    const float* x     = (const float*)d_in[0];
    const float* wts   = (const float*)d_in[1];
    const float* Wmlp  = (const float*)d_in[2];
    const float* bmlp  = (const float*)d_in[3];
    const float* Wl    = (const float*)d_in[4];
    const float* Wr    = (const float*)d_in[5];
    const float* bsage = (const float*)d_in[6];
    const float* Wgcn  = (const float*)d_in[7];
    const float* bgcn  = (const float*)d_in[8];
    const float* Wgat  = (const float*)d_in[9];
    const float* asrc  = (const float*)d_in[10];
    const float* adst  = (const float*)d_in[11];
    const float* bgat  = (const float*)d_in[12];
    const float* Wcheb = (const float*)d_in[13];
    const float* bcheb = (const float*)d_in[14];
    const float* Wgin  = (const float*)d_in[15];
    const float* bgin  = (const float*)d_in[16];
    const void*  eidx  = d_in[17];
    float* out = (float*)d_out;

    int N = in_sizes[0] / 64;
    if (N > NMAX) N = NMAX;
    int E = in_sizes[17] / 2;
    if (E > EMAX) E = EMAX;

    int nb_node = (N + 127) / 128;
    int nb_warp = (N * 32 + 255) / 256;
    int G = (N + 255) / 256;   // scan blocks (<= 256 for N <= 65536)

    kdetect<<<1, 32>>>((const int*)eidx);
    kzeroh<<<G, 256>>>(N);
    kconvert<<<(E + 255) / 256, 256>>>(eidx, E);
    kbsum<<<G, 256>>>(N);
    kbscan<<<1, 256>>>(G);
    kapply<<<G, 256>>>(N, E);
    kscatter<<<(E + 255) / 256, 256>>>(E);
    k1a<<<nb_node, 256>>>(x, wts, Wmlp, bmlp, Wgcn, Wgat, asrc, adst, Wr, bsage,
                          Wgin, bgin, out, N);
    kaggA<<<nb_warp, 256>>>(x, N);
    k1b<<<nb_node, 256>>>(wts, Wl, Wgin, out, N);
    kaggB<<<nb_warp, 256>>>(N);
    kf<<<nb_node, 256>>>(x, wts, Wcheb, bcheb, bgcn, bgat, out, N);
}